// round 12
// baseline (speedup 1.0000x reference)
#include <cuda_runtime.h>
#include <cuda_bf16.h>
#include <mma.h>
#include <math.h>
#include <stdint.h>

using namespace nvcuda;

#define B_   32
#define C_   128
#define H_   56
#define W_   56
#define P_   (H_*W_)
#define E_   4
#define OUT_MAIN ((size_t)B_*C_*P_)

// k-offsets into the presplit weight banks (units of K rows, each row = 128 co)
#define KOFF_SH    0        // shared 3x3:          K=1152
#define KOFF_SHCD  1152     // shared+cd fused 3x3: K=1152
#define KOFF_BAYAR 2304     // bayar 5x5:           K=3200
#define KOFF_SRM   5504     // srm 1x1:             K=384
#define KOFF_HF    5888     // hf 1x1:              K=128
#define KTOT       6016

// ---------------- scratch (device globals; no allocs allowed) ----------------
__device__ float g_pooled[B_*C_];
__device__ int   g_assign[B_];
__device__ float g_weights[B_*E_];
__device__ __nv_bfloat16 g_w0[(size_t)KTOT*128];  // bf16 major parts, [k][co]
__device__ __nv_bfloat16 g_w1[(size_t)KTOT*128];  // bf16 residual parts
__device__ float g_y[(size_t)B_*3*C_*P_];  // srm dw out (B,384,P); reused as hf dw out
__device__ float g_z1[(size_t)B_*C_*P_];   // srm 1x1 out
__device__ float g_z2[(size_t)B_*C_*P_];   // hf 1x1 out
__device__ float g_mean1[C_], g_inv1[C_];
__device__ float g_mean2[C_], g_inv2[C_];

// bf16 2-way split: v = b0 + b1 + O(2^-17 v)
__device__ __forceinline__ void split_bf(float v, __nv_bfloat16& b0, __nv_bfloat16& b1) {
    b0 = __float2bfloat16_rn(v);
    b1 = __float2bfloat16_rn(v - __bfloat162float(b0));
}
__device__ __forceinline__ void wsplit(float v, size_t d) {
    __nv_bfloat16 b0, b1;
    split_bf(v, b0, b1);
    g_w0[d] = b0; g_w1[d] = b1;
}

// ---------------- pooling ----------------
__global__ void pool_kernel(const float* __restrict__ x) {
    int bc = blockIdx.x;
    float s = 0.f;
    for (int p = threadIdx.x; p < P_; p += 256)
        s += x[(size_t)bc*P_ + p];
    __shared__ float sh[256];
    sh[threadIdx.x] = s;
    __syncthreads();
    for (int st = 128; st > 0; st >>= 1) {
        if (threadIdx.x < st) sh[threadIdx.x] += sh[threadIdx.x + st];
        __syncthreads();
    }
    if (threadIdx.x == 0) g_pooled[bc] = sh[0] / (float)P_;
}

// ---------------- gating + tail outputs ----------------
__global__ void gate_kernel(const float* __restrict__ Wg, float* __restrict__ out_tail,
                            int write_tail) {
    int tid = threadIdx.x;
    if (tid < B_) {
        float l[E_] = {0.f,0.f,0.f,0.f};
        for (int c = 0; c < C_; c++) {
            float p = g_pooled[tid*C_ + c];
            #pragma unroll
            for (int e = 0; e < E_; e++) l[e] += p * Wg[c*E_ + e];
        }
        int best = 0; float bv = l[0];
        #pragma unroll
        for (int e = 1; e < E_; e++) if (l[e] > bv) { bv = l[e]; best = e; }
        g_assign[tid] = best;
        #pragma unroll
        for (int e = 0; e < E_; e++) g_weights[tid*E_ + e] = (e == best) ? 1.f : 0.f;
    }
    __syncthreads();
    if (tid == 0 && write_tail) {
        float cnt[E_] = {0.f,0.f,0.f,0.f};
        for (int b = 0; b < B_; b++) cnt[g_assign[b]] += 1.f;
        float mean = (float)B_ / (float)E_;
        float var = 0.f;
        for (int e = 0; e < E_; e++) { float d = cnt[e]-mean; var += d*d; }
        var /= (float)E_;
        out_tail[0] = var / (mean*mean + 1e-10f);
        for (int e = 0; e < E_; e++) out_tail[1+e] = cnt[e];
        for (int e = 0; e < E_; e++) out_tail[5+e] = cnt[e];
        for (int i = 0; i < B_*E_; i++) out_tail[9+i] = g_weights[i];
    }
}

// ---------------- weight prep ----------------
__global__ void prep_shcd_kernel(const float* __restrict__ wsh, const float* __restrict__ wcd) {
    int idx = blockIdx.x*256 + threadIdx.x;
    if (idx >= C_*C_) return;
    int co = idx >> 7, ci = idx & 127;
    float vs[9], vc[9]; float s = 0.f;
    #pragma unroll
    for (int t = 0; t < 9; t++) {
        vs[t] = wsh[(co*C_ + ci)*9 + t];
        vc[t] = wcd[(co*C_ + ci)*9 + t];
        s += vc[t];
    }
    vc[4] -= 0.7f * s;
    #pragma unroll
    for (int t = 0; t < 9; t++) {
        size_t row = (size_t)(t*C_ + ci);
        wsplit(vs[t],          (KOFF_SH   + row)*128 + co);
        wsplit(vs[t] + vc[t],  (KOFF_SHCD + row)*128 + co);
    }
}

__global__ void prep5_kernel(const float* __restrict__ raw, int koff) {
    int idx = blockIdx.x*256 + threadIdx.x;
    if (idx >= C_*C_) return;
    int co = idx >> 7, ci = idx & 127;
    float v[24]; float s = 0.f;
    #pragma unroll
    for (int t = 0; t < 24; t++) { v[t] = raw[(co*C_ + ci)*24 + t]; s += v[t]; }
    float invs = 1.f / s;
    #pragma unroll
    for (int t = 0; t < 25; t++) {
        float wv = (t == 12) ? -1.f : (t < 12 ? v[t]*invs : v[t-1]*invs);
        wsplit(wv, ((size_t)(koff + t*C_ + ci))*128 + co);
    }
}

template<int CIN>
__global__ void prep1_kernel(const float* __restrict__ w, int koff) {
    int idx = blockIdx.x*256 + threadIdx.x;
    if (idx >= C_*CIN) return;
    int co = idx / CIN, ci = idx % CIN;
    wsplit(w[(size_t)co*CIN + ci], ((size_t)(koff + ci))*128 + co);
}

// ---------------- implicit-GEMM conv via wmma bf16 (3-product split), 2-row blocks ------
// Block: 256 thr (8 warps): 128 co x 128 px (image rows h0, h0+1 of batch b).
// Warp tile: 64 co x 32 px (4x2 m16n16k16). K chunks of 32 (tap-major).
// SRC: 0=xparam, 1=g_y. DST: 0=outparam, 1=g_z1, 2=g_z2.
// FUSE: weight bank by g_assign[b] (KOFF_SHCD for expert-0 samples, else KOFF_SH).
template<int CIN, int KW, int PAD, bool ACCUM, int SRC, int DST, bool FUSE>
__global__ __launch_bounds__(256, 2)
void conv_wmma_kernel(const float* __restrict__ xparam, int woff,
                      float* __restrict__ outparam, int sel) {
    const int h0 = blockIdx.x * 2;
    const int b  = blockIdx.y;
    if (sel >= 0 && g_assign[b] != sel) return;
    const int wbase = FUSE ? (g_assign[b] == 0 ? KOFF_SHCD : KOFF_SH) : woff;

    const float* xin = (SRC == 0) ? xparam : (const float*)g_y;
    float* outp      = (DST == 0) ? outparam : (DST == 1) ? (float*)g_z1 : (float*)g_z2;

    __shared__ __align__(16) char smraw[36864];
    __nv_bfloat16* As0 = (__nv_bfloat16*)smraw;   // [32][136] px 0..127 (+pad)
    __nv_bfloat16* As1 = As0 + 4352;              // [32][136]
    __nv_bfloat16* W0  = As1 + 4352;              // [32][136] co 0..127 (+pad)
    __nv_bfloat16* W1  = W0 + 4352;               // [32][136]
    float* Cs = (float*)smraw;                    // [128][72] epilogue staging (per row pass)

    const int tid = threadIdx.x;
    const int wid = tid >> 5;
    const int wco = (wid & 1) * 64;   // warp co base (2 halves)
    const int wpx = (wid >> 1) * 32;  // warp px base (4 quarters over 128 px)

    typedef wmma::fragment<wmma::matrix_a, 16, 16, 16, __nv_bfloat16, wmma::col_major> FragA;
    typedef wmma::fragment<wmma::matrix_b, 16, 16, 16, __nv_bfloat16, wmma::row_major> FragB;
    typedef wmma::fragment<wmma::accumulator, 16, 16, 16, float> FragC;

    FragC acc[4][2];
    #pragma unroll
    for (int mi = 0; mi < 4; mi++)
        #pragma unroll
        for (int ni = 0; ni < 2; ni++)
            wmma::fill_fragment(acc[mi][ni], 0.f);

    constexpr int K = KW*KW*CIN;
    const int lr  = tid >> 3;           // 0..31 smem k-row
    const int lcA = (tid & 7) * 16;     // As: 16 px per thread (stays in one row-half)
    const int rhalf = lcA >> 6;         // 0: row h0, 1: row h0+1
    const int cbase = lcA & 63;
    const int lcW = (tid & 7) * 16;     // W: 16 co per thread

    for (int kk = 0; kk < K; kk += 32) {
        const int tap = kk / CIN;
        const int ci0 = kk % CIN;
        const int dy = tap / KW - PAD, dx = tap % KW - PAD;
        const int hs = h0 + rhalf + dy;
        const bool rok = (hs >= 0) && (hs < H_);
        __syncthreads();
        // im2col: 32 ci x 128 px (two shifted rows, zero padded), split to bf16 pair
        {
            const float* src = xin + ((size_t)(b*CIN + ci0 + lr))*(size_t)P_
                                   + (size_t)(rok ? hs : 0)*W_;
            #pragma unroll
            for (int j = 0; j < 16; j++) {
                int sc = cbase + j + dx;
                float v = (rok && sc >= 0 && sc < W_) ? src[sc] : 0.f;
                __nv_bfloat16 b0, b1;
                split_bf(v, b0, b1);
                As0[lr*136 + lcA + j] = b0;
                As1[lr*136 + lcA + j] = b1;
            }
        }
        // weights: copy presplit rows [k][128]
        {
            const uint4* s0 = (const uint4*)(g_w0 + ((size_t)(wbase + kk + lr))*128 + lcW);
            const uint4* s1 = (const uint4*)(g_w1 + ((size_t)(wbase + kk + lr))*128 + lcW);
            uint4* d0 = (uint4*)(W0 + lr*136 + lcW);
            uint4* d1 = (uint4*)(W1 + lr*136 + lcW);
            d0[0] = s0[0]; d0[1] = s0[1];
            d1[0] = s1[0]; d1[1] = s1[1];
        }
        __syncthreads();
        #pragma unroll
        for (int ks = 0; ks < 2; ks++) {
            const int k0 = ks * 16;
            FragB b0f[2], b1f[2];
            #pragma unroll
            for (int ni = 0; ni < 2; ni++) {
                wmma::load_matrix_sync(b0f[ni], As0 + (size_t)k0*136 + wpx + ni*16, 136);
                wmma::load_matrix_sync(b1f[ni], As1 + (size_t)k0*136 + wpx + ni*16, 136);
            }
            #pragma unroll
            for (int mi = 0; mi < 4; mi++) {
                FragA a0f, a1f;
                wmma::load_matrix_sync(a0f, W0 + (size_t)k0*136 + wco + mi*16, 136);
                wmma::load_matrix_sync(a1f, W1 + (size_t)k0*136 + wco + mi*16, 136);
                #pragma unroll
                for (int ni = 0; ni < 2; ni++) {
                    wmma::mma_sync(acc[mi][ni], a0f, b0f[ni], acc[mi][ni]);
                    wmma::mma_sync(acc[mi][ni], a0f, b1f[ni], acc[mi][ni]);
                    wmma::mma_sync(acc[mi][ni], a1f, b0f[ni], acc[mi][ni]);
                }
            }
        }
    }

    // epilogue: two passes (one per image row), staged through Cs [128co][72px]
    #pragma unroll
    for (int pass = 0; pass < 2; pass++) {
        __syncthreads();
        if ((wpx >> 6) == pass) {
            #pragma unroll
            for (int mi = 0; mi < 4; mi++)
                #pragma unroll
                for (int ni = 0; ni < 2; ni++)
                    wmma::store_matrix_sync(Cs + (size_t)(wco + mi*16)*72 + (wpx & 63) + ni*16,
                                            acc[mi][ni], 72, wmma::mem_row_major);
        }
        __syncthreads();
        const size_t obase = (size_t)b*C_*(size_t)P_ + (size_t)(h0 + pass)*W_;
        for (int idx = tid; idx < C_*W_; idx += 256) {
            int co = idx / W_, px = idx % W_;
            float v = Cs[co*72 + px];
            size_t o = obase + (size_t)co*P_ + px;
            if (ACCUM) outp[o] += v; else outp[o] = v;
        }
    }
}

// ---------------- srm depthwise 5x5 + hardtanh ----------------
__global__ void dw_srm_kernel(const float* __restrict__ x, const float* __restrict__ kern) {
    int b = blockIdx.x / C_, c = blockIdx.x % C_;
    __shared__ float xs[60][60];
    __shared__ float kf[3][25];
    int tid = threadIdx.x;  // 256
    for (int idx = tid; idx < 60*60; idx += 256) {
        int ry = idx / 60, rx = idx % 60;
        int hh = ry - 2, wi = rx - 2;
        float v = 0.f;
        if (hh >= 0 && hh < H_ && wi >= 0 && wi < W_)
            v = x[((size_t)(b*C_ + c)*H_ + hh)*W_ + wi];
        xs[ry][rx] = v;
    }
    if (tid < 75) kf[tid/25][tid%25] = kern[(c*3 + tid/25)*25 + tid%25];
    __syncthreads();
    for (int p = tid; p < P_; p += 256) {
        int hh = p / W_, wi = p % W_;
        float a0 = 0.f, a1 = 0.f, a2 = 0.f;
        #pragma unroll
        for (int ky = 0; ky < 5; ky++)
            #pragma unroll
            for (int kx = 0; kx < 5; kx++) {
                float v = xs[hh+ky][wi+kx];
                a0 += kf[0][ky*5+kx]*v;
                a1 += kf[1][ky*5+kx]*v;
                a2 += kf[2][ky*5+kx]*v;
            }
        a0 = fminf(fmaxf(a0, -3.f), 3.f);
        a1 = fminf(fmaxf(a1, -3.f), 3.f);
        a2 = fminf(fmaxf(a2, -3.f), 3.f);
        size_t base = ((size_t)b*3*C_ + c*3)*P_ + p;
        g_y[base        ] = a0;
        g_y[base +   P_ ] = a1;
        g_y[base + 2*P_ ] = a2;
    }
}

// ---------------- hf depthwise 3x3 ----------------
__global__ void dw_hf_kernel(const float* __restrict__ x, const float* __restrict__ kern) {
    int b = blockIdx.x / C_, c = blockIdx.x % C_;
    __shared__ float xs[58][58];
    __shared__ float kf[9];
    int tid = threadIdx.x;  // 256
    for (int idx = tid; idx < 58*58; idx += 256) {
        int ry = idx / 58, rx = idx % 58;
        int hh = ry - 1, wi = rx - 1;
        float v = 0.f;
        if (hh >= 0 && hh < H_ && wi >= 0 && wi < W_)
            v = x[((size_t)(b*C_ + c)*H_ + hh)*W_ + wi];
        xs[ry][rx] = v;
    }
    if (tid < 9) kf[tid] = kern[c*9 + tid];
    __syncthreads();
    for (int p = tid; p < P_; p += 256) {
        int hh = p / W_, wi = p % W_;
        float a = 0.f;
        #pragma unroll
        for (int ky = 0; ky < 3; ky++)
            #pragma unroll
            for (int kx = 0; kx < 3; kx++)
                a += kf[ky*3+kx] * xs[hh+ky][wi+kx];
        g_y[((size_t)(b*C_ + c))*P_ + p] = a;
    }
}

// ---------------- BN statistics over (B,H,W) per channel ----------------
__global__ void bn_stats2_kernel(int zsel) {
    const float* z = (zsel == 0) ? g_z1 : g_z2;
    int c = blockIdx.x;
    double s = 0.0, s2 = 0.0;
    for (int t = threadIdx.x; t < B_*(P_/4); t += 256) {
        int b = t / (P_/4), q = t % (P_/4);
        float4 v = ((const float4*)&z[((size_t)(b*C_ + c))*P_])[q];
        s  += (double)v.x + (double)v.y + (double)v.z + (double)v.w;
        s2 += (double)v.x*v.x + (double)v.y*v.y + (double)v.z*v.z + (double)v.w*v.w;
    }
    __shared__ double sh[256], sh2[256];
    sh[threadIdx.x] = s; sh2[threadIdx.x] = s2;
    __syncthreads();
    for (int st = 128; st > 0; st >>= 1) {
        if (threadIdx.x < st) { sh[threadIdx.x] += sh[threadIdx.x+st]; sh2[threadIdx.x] += sh2[threadIdx.x+st]; }
        __syncthreads();
    }
    if (threadIdx.x == 0) {
        double n = (double)B_*P_;
        double m = sh[0] / n;
        double var = sh2[0] / n - m*m;
        if (zsel == 0) { g_mean1[c] = (float)m; g_inv1[c] = (float)(1.0 / sqrt(var + 1e-5)); }
        else           { g_mean2[c] = (float)m; g_inv2[c] = (float)(1.0 / sqrt(var + 1e-5)); }
    }
}

// ---------------- BN apply + ReLU + gated accumulate ----------------
__global__ void bn_apply2_kernel(float* __restrict__ out, const float* __restrict__ gamma,
                                 const float* __restrict__ beta, int zsel, int sel) {
    int b = blockIdx.x / C_, c = blockIdx.x % C_;
    if (g_assign[b] != sel) return;
    const float* z = (zsel == 0) ? g_z1 : g_z2;
    float m   = (zsel == 0) ? g_mean1[c] : g_mean2[c];
    float inv = (zsel == 0) ? g_inv1[c]  : g_inv2[c];
    float sc = inv * gamma[c];
    float shft = beta[c] - m * sc;
    const float4* zp = (const float4*)&z[((size_t)(b*C_ + c))*P_];
    float4* op = (float4*)&out[((size_t)(b*C_ + c))*P_];
    for (int q = threadIdx.x; q < P_/4; q += 256) {
        float4 v = zp[q];
        float4 o = op[q];
        o.x += fmaxf(v.x*sc + shft, 0.f);
        o.y += fmaxf(v.y*sc + shft, 0.f);
        o.z += fmaxf(v.z*sc + shft, 0.f);
        o.w += fmaxf(v.w*sc + shft, 0.f);
        op[q] = o;
    }
}

// ---------------- launch (single stream, capture-safe) ----------------
extern "C" void kernel_launch(void* const* d_in, const int* in_sizes, int n_in,
                              void* d_out, int out_size) {
    const float* x          = (const float*)d_in[0];
    const float* Wg         = (const float*)d_in[1];
    const float* cd_w       = (const float*)d_in[2];
    const float* bayar_w    = (const float*)d_in[3];
    const float* srm_kernel = (const float*)d_in[4];
    const float* srm_out_w  = (const float*)d_in[5];
    const float* srm_gamma  = (const float*)d_in[6];
    const float* srm_beta   = (const float*)d_in[7];
    const float* hf_kernel  = (const float*)d_in[8];
    const float* hf_out_w   = (const float*)d_in[9];
    const float* hf_gamma   = (const float*)d_in[10];
    const float* hf_beta    = (const float*)d_in[11];
    const float* shared_w   = (const float*)d_in[12];
    float* out = (float*)d_out;

    int write_tail = ((size_t)out_size >= OUT_MAIN + 137) ? 1 : 0;

    const dim3 cg(H_/2, B_);   // 28 x 32 blocks; each 128co x 128px (2 rows)

    pool_kernel<<<B_*C_, 256>>>(x);                                             // 1
    gate_kernel<<<1, 128>>>(Wg, out + OUT_MAIN, write_tail);                    // 2
    prep_shcd_kernel<<<64, 256>>>(shared_w, cd_w);                              // 3
    // fused shared(+cd for expert-0 samples) 3x3, full batch
    conv_wmma_kernel<C_,3,1,false,0,0,true><<<cg, 256>>>(x, 0, out, -1);        // 4 (ncu slot)
    prep5_kernel<<<64, 256>>>(bayar_w, KOFF_BAYAR);                             // 5
    conv_wmma_kernel<C_,5,2,true,0,0,false><<<cg, 256>>>(x, KOFF_BAYAR, out, 1);// 6 bayar gated

    // srm expert: full batch (BN stats), gated add
    dw_srm_kernel<<<B_*C_, 256>>>(x, srm_kernel);
    prep1_kernel<3*C_><<<192, 256>>>(srm_out_w, KOFF_SRM);
    conv_wmma_kernel<3*C_,1,0,false,1,1,false><<<cg, 256>>>(x, KOFF_SRM, out, -1); // g_y -> g_z1
    bn_stats2_kernel<<<C_, 256>>>(0);
    bn_apply2_kernel<<<B_*C_, 256>>>(out, srm_gamma, srm_beta, 0, 2);

    // hf expert: full batch, gated add
    dw_hf_kernel<<<B_*C_, 256>>>(x, hf_kernel);
    prep1_kernel<C_><<<64, 256>>>(hf_out_w, KOFF_HF);
    conv_wmma_kernel<C_,1,0,false,1,2,false><<<cg, 256>>>(x, KOFF_HF, out, -1);    // g_y -> g_z2
    bn_stats2_kernel<<<C_, 256>>>(1);
    bn_apply2_kernel<<<B_*C_, 256>>>(out, hf_gamma, hf_beta, 1, 3);
}

// round 14
// speedup vs baseline: 1.1620x; 1.1620x over previous
#include <cuda_runtime.h>
#include <cuda_bf16.h>
#include <mma.h>
#include <math.h>
#include <stdint.h>

using namespace nvcuda;

#define B_   32
#define C_   128
#define H_   56
#define W_   56
#define P_   (H_*W_)
#define E_   4
#define OUT_MAIN ((size_t)B_*C_*P_)

// k-offsets into the presplit weight banks (units of K rows, each row = 128 co)
#define KOFF_SH    0        // shared 3x3:          K=1152
#define KOFF_SHCD  1152     // shared+cd fused 3x3: K=1152
#define KOFF_BAYAR 2304     // bayar 5x5:           K=3200
#define KOFF_SRM   5504     // srm 1x1:             K=384
#define KOFF_HF    5888     // hf 1x1:              K=128
#define KTOT       6016

// dynamic smem: 2 stages x (As0+As1+W0+W1) x 4352 bf16 = 69632 bytes
#define STAGE_ELEMS 17408
#define SMEM_DYN    69632

// ---------------- scratch (device globals; no allocs allowed) ----------------
__device__ float g_pooled[B_*C_];
__device__ int   g_assign[B_];
__device__ float g_weights[B_*E_];
__device__ __nv_bfloat16 g_w0[(size_t)KTOT*128];  // bf16 major parts, [k][co]
__device__ __nv_bfloat16 g_w1[(size_t)KTOT*128];  // bf16 residual parts
__device__ float g_y[(size_t)B_*3*C_*P_];  // srm dw out (B,384,P); reused as hf dw out
__device__ float g_z1[(size_t)B_*C_*P_];   // srm 1x1 out
__device__ float g_z2[(size_t)B_*C_*P_];   // hf 1x1 out
__device__ float g_mean1[C_], g_inv1[C_];
__device__ float g_mean2[C_], g_inv2[C_];

// bf16 2-way split: v = b0 + b1 + O(2^-17 v)
__device__ __forceinline__ void split_bf(float v, __nv_bfloat16& b0, __nv_bfloat16& b1) {
    b0 = __float2bfloat16_rn(v);
    b1 = __float2bfloat16_rn(v - __bfloat162float(b0));
}
__device__ __forceinline__ void wsplit(float v, size_t d) {
    __nv_bfloat16 b0, b1;
    split_bf(v, b0, b1);
    g_w0[d] = b0; g_w1[d] = b1;
}

// ---------------- pooling ----------------
__global__ void pool_kernel(const float* __restrict__ x) {
    int bc = blockIdx.x;
    float s = 0.f;
    for (int p = threadIdx.x; p < P_; p += 256)
        s += x[(size_t)bc*P_ + p];
    __shared__ float sh[256];
    sh[threadIdx.x] = s;
    __syncthreads();
    for (int st = 128; st > 0; st >>= 1) {
        if (threadIdx.x < st) sh[threadIdx.x] += sh[threadIdx.x + st];
        __syncthreads();
    }
    if (threadIdx.x == 0) g_pooled[bc] = sh[0] / (float)P_;
}

// ---------------- gating + tail outputs ----------------
__global__ void gate_kernel(const float* __restrict__ Wg, float* __restrict__ out_tail,
                            int write_tail) {
    int tid = threadIdx.x;
    if (tid < B_) {
        float l[E_] = {0.f,0.f,0.f,0.f};
        for (int c = 0; c < C_; c++) {
            float p = g_pooled[tid*C_ + c];
            #pragma unroll
            for (int e = 0; e < E_; e++) l[e] += p * Wg[c*E_ + e];
        }
        int best = 0; float bv = l[0];
        #pragma unroll
        for (int e = 1; e < E_; e++) if (l[e] > bv) { bv = l[e]; best = e; }
        g_assign[tid] = best;
        #pragma unroll
        for (int e = 0; e < E_; e++) g_weights[tid*E_ + e] = (e == best) ? 1.f : 0.f;
    }
    __syncthreads();
    if (tid == 0 && write_tail) {
        float cnt[E_] = {0.f,0.f,0.f,0.f};
        for (int b = 0; b < B_; b++) cnt[g_assign[b]] += 1.f;
        float mean = (float)B_ / (float)E_;
        float var = 0.f;
        for (int e = 0; e < E_; e++) { float d = cnt[e]-mean; var += d*d; }
        var /= (float)E_;
        out_tail[0] = var / (mean*mean + 1e-10f);
        for (int e = 0; e < E_; e++) out_tail[1+e] = cnt[e];
        for (int e = 0; e < E_; e++) out_tail[5+e] = cnt[e];
        for (int i = 0; i < B_*E_; i++) out_tail[9+i] = g_weights[i];
    }
}

// ---------------- weight prep ----------------
__global__ void prep_shcd_kernel(const float* __restrict__ wsh, const float* __restrict__ wcd) {
    int idx = blockIdx.x*256 + threadIdx.x;
    if (idx >= C_*C_) return;
    int co = idx >> 7, ci = idx & 127;
    float vs[9], vc[9]; float s = 0.f;
    #pragma unroll
    for (int t = 0; t < 9; t++) {
        vs[t] = wsh[(co*C_ + ci)*9 + t];
        vc[t] = wcd[(co*C_ + ci)*9 + t];
        s += vc[t];
    }
    vc[4] -= 0.7f * s;
    #pragma unroll
    for (int t = 0; t < 9; t++) {
        size_t row = (size_t)(t*C_ + ci);
        wsplit(vs[t],          (KOFF_SH   + row)*128 + co);
        wsplit(vs[t] + vc[t],  (KOFF_SHCD + row)*128 + co);
    }
}

__global__ void prep5_kernel(const float* __restrict__ raw, int koff) {
    int idx = blockIdx.x*256 + threadIdx.x;
    if (idx >= C_*C_) return;
    int co = idx >> 7, ci = idx & 127;
    float v[24]; float s = 0.f;
    #pragma unroll
    for (int t = 0; t < 24; t++) { v[t] = raw[(co*C_ + ci)*24 + t]; s += v[t]; }
    float invs = 1.f / s;
    #pragma unroll
    for (int t = 0; t < 25; t++) {
        float wv = (t == 12) ? -1.f : (t < 12 ? v[t]*invs : v[t-1]*invs);
        wsplit(wv, ((size_t)(koff + t*C_ + ci))*128 + co);
    }
}

template<int CIN>
__global__ void prep1_kernel(const float* __restrict__ w, int koff) {
    int idx = blockIdx.x*256 + threadIdx.x;
    if (idx >= C_*CIN) return;
    int co = idx / CIN, ci = idx % CIN;
    wsplit(w[(size_t)co*CIN + ci], ((size_t)(koff + ci))*128 + co);
}

// ---------------- implicit-GEMM conv: wmma bf16 3-product, 2-stage pipeline ----------
// Block: 256 thr (8 warps): 128 co x 128 px (image rows h0, h0+1 of batch b).
// Warp tile: 64 co x 32 px (4x2 m16n16k16). K chunks of 32 (tap-major).
// Pipeline: weights via cp.async into next stage; im2col prefetched to regs, split+stored
// after the mma; one __syncthreads per chunk.
template<int CIN, int KW, int PAD, bool ACCUM, int SRC, int DST, bool FUSE>
__global__ __launch_bounds__(256, 2)
void conv_wmma_kernel(const float* __restrict__ xparam, int woff,
                      float* __restrict__ outparam, int sel) {
    const int h0 = blockIdx.x * 2;
    const int b  = blockIdx.y;
    if (sel >= 0 && g_assign[b] != sel) return;
    const int wbase = FUSE ? (g_assign[b] == 0 ? KOFF_SHCD : KOFF_SH) : woff;

    const float* xin = (SRC == 0) ? xparam : (const float*)g_y;
    float* outp      = (DST == 0) ? outparam : (DST == 1) ? (float*)g_z1 : (float*)g_z2;

    extern __shared__ __align__(16) char smraw[];
    __nv_bfloat16* sm = (__nv_bfloat16*)smraw;
    // stage s (s=0,1) base = s*STAGE_ELEMS: As0 +0, As1 +4352, W0 +8704, W1 +13056

    const int tid = threadIdx.x;
    const int wid = tid >> 5;
    const int wco = (wid & 1) * 64;   // warp co base
    const int wpx = (wid >> 1) * 32;  // warp px base (over 128 px = 2 rows)

    typedef wmma::fragment<wmma::matrix_a, 16, 16, 16, __nv_bfloat16, wmma::col_major> FragA;
    typedef wmma::fragment<wmma::matrix_b, 16, 16, 16, __nv_bfloat16, wmma::row_major> FragB;
    typedef wmma::fragment<wmma::accumulator, 16, 16, 16, float> FragC;

    FragC acc[4][2];
    #pragma unroll
    for (int mi = 0; mi < 4; mi++)
        #pragma unroll
        for (int ni = 0; ni < 2; ni++)
            wmma::fill_fragment(acc[mi][ni], 0.f);

    constexpr int K = KW*KW*CIN;
    constexpr int NCH = K / 32;
    const int lr  = tid >> 3;           // 0..31 k-row
    const int lcA = (tid & 7) * 16;     // im2col: 16 px per thread
    const int rhalf = lcA >> 6;         // 0: row h0, 1: row h0+1
    const int cbase = lcA & 63;
    const int lcW = (tid & 7) * 16;     // weights: 16 co per thread

    float xv[16];

    // -- helpers (inlined) --
    #define LD_IM2COL(KKv)                                                            \
        do {                                                                          \
            const int tap_ = (KKv) / CIN;                                             \
            const int ci0_ = (KKv) % CIN;                                             \
            const int dy_ = tap_ / KW - PAD, dx_ = tap_ % KW - PAD;                   \
            const int hs_ = h0 + rhalf + dy_;                                         \
            const bool rok_ = (hs_ >= 0) && (hs_ < H_);                               \
            const float* src_ = xin + ((size_t)(b*CIN + ci0_ + lr))*(size_t)P_        \
                                    + (size_t)(rok_ ? hs_ : 0)*W_;                    \
            _Pragma("unroll")                                                         \
            for (int j = 0; j < 16; j++) {                                            \
                int sc_ = cbase + j + dx_;                                            \
                xv[j] = (rok_ && sc_ >= 0 && sc_ < W_) ? src_[sc_] : 0.f;             \
            }                                                                         \
        } while (0)

    #define CP_W(KKv, STG)                                                            \
        do {                                                                          \
            const __nv_bfloat16* s0_ = g_w0 + ((size_t)(wbase + (KKv) + lr))*128 + lcW; \
            const __nv_bfloat16* s1_ = g_w1 + ((size_t)(wbase + (KKv) + lr))*128 + lcW; \
            uint32_t d0_ = (uint32_t)__cvta_generic_to_shared(                        \
                sm + (STG)*STAGE_ELEMS + 8704 + lr*136 + lcW);                        \
            uint32_t d1_ = (uint32_t)__cvta_generic_to_shared(                        \
                sm + (STG)*STAGE_ELEMS + 13056 + lr*136 + lcW);                       \
            asm volatile(                                                             \
                "cp.async.cg.shared.global [%0], [%1], 16;\n\t"                       \
                "cp.async.cg.shared.global [%2], [%3], 16;\n\t"                       \
                "cp.async.cg.shared.global [%4], [%5], 16;\n\t"                       \
                "cp.async.cg.shared.global [%6], [%7], 16;\n\t"                       \
                "cp.async.commit_group;"                                              \
                :: "r"(d0_), "l"(s0_), "r"(d0_+16), "l"((const char*)s0_+16),         \
                   "r"(d1_), "l"(s1_), "r"(d1_+16), "l"((const char*)s1_+16));        \
        } while (0)

    #define ST_IM2COL(STG)                                                            \
        do {                                                                          \
            __nv_bfloat16* A0_ = sm + (STG)*STAGE_ELEMS + lr*136 + lcA;               \
            __nv_bfloat16* A1_ = A0_ + 4352;                                          \
            _Pragma("unroll")                                                         \
            for (int j = 0; j < 16; j++) {                                            \
                __nv_bfloat16 b0_, b1_;                                               \
                split_bf(xv[j], b0_, b1_);                                            \
                A0_[j] = b0_; A1_[j] = b1_;                                           \
            }                                                                         \
        } while (0)

    // -- prologue: fill stage 0 --
    LD_IM2COL(0);
    CP_W(0, 0);
    ST_IM2COL(0);
    asm volatile("cp.async.wait_group 0;");
    __syncthreads();

    for (int i = 0; i < NCH; i++) {
        const int cur = i & 1, nxt = cur ^ 1;
        if (i + 1 < NCH) {
            LD_IM2COL((i + 1) * 32);   // gmem loads in flight during mma
            CP_W((i + 1) * 32, nxt);
        }
        // -- mma on stage cur --
        {
            const __nv_bfloat16* As0 = sm + cur*STAGE_ELEMS;
            const __nv_bfloat16* As1 = As0 + 4352;
            const __nv_bfloat16* W0  = As0 + 8704;
            const __nv_bfloat16* W1  = As0 + 13056;
            #pragma unroll
            for (int ks = 0; ks < 2; ks++) {
                const int k0 = ks * 16;
                FragB b0f[2], b1f[2];
                #pragma unroll
                for (int ni = 0; ni < 2; ni++) {
                    wmma::load_matrix_sync(b0f[ni], As0 + (size_t)k0*136 + wpx + ni*16, 136);
                    wmma::load_matrix_sync(b1f[ni], As1 + (size_t)k0*136 + wpx + ni*16, 136);
                }
                #pragma unroll
                for (int mi = 0; mi < 4; mi++) {
                    FragA a0f, a1f;
                    wmma::load_matrix_sync(a0f, W0 + (size_t)k0*136 + wco + mi*16, 136);
                    wmma::load_matrix_sync(a1f, W1 + (size_t)k0*136 + wco + mi*16, 136);
                    #pragma unroll
                    for (int ni = 0; ni < 2; ni++) {
                        wmma::mma_sync(acc[mi][ni], a0f, b0f[ni], acc[mi][ni]);
                        wmma::mma_sync(acc[mi][ni], a0f, b1f[ni], acc[mi][ni]);
                        wmma::mma_sync(acc[mi][ni], a1f, b0f[ni], acc[mi][ni]);
                    }
                }
            }
        }
        if (i + 1 < NCH) {
            ST_IM2COL(nxt);
            asm volatile("cp.async.wait_group 0;");
        }
        __syncthreads();
    }

    #undef LD_IM2COL
    #undef CP_W
    #undef ST_IM2COL

    // -- epilogue: two passes (one per image row), staged through Cs [128co][72px] --
    float* Cs = (float*)smraw;
    #pragma unroll
    for (int pass = 0; pass < 2; pass++) {
        __syncthreads();
        if ((wpx >> 6) == pass) {
            #pragma unroll
            for (int mi = 0; mi < 4; mi++)
                #pragma unroll
                for (int ni = 0; ni < 2; ni++)
                    wmma::store_matrix_sync(Cs + (size_t)(wco + mi*16)*72 + (wpx & 63) + ni*16,
                                            acc[mi][ni], 72, wmma::mem_row_major);
        }
        __syncthreads();
        const size_t obase = (size_t)b*C_*(size_t)P_ + (size_t)(h0 + pass)*W_;
        for (int idx = tid; idx < C_*W_; idx += 256) {
            int co = idx / W_, px = idx % W_;
            float v = Cs[co*72 + px];
            size_t o = obase + (size_t)co*P_ + px;
            if (ACCUM) outp[o] += v; else outp[o] = v;
        }
    }
}

// ---------------- srm depthwise 5x5 + hardtanh ----------------
__global__ void dw_srm_kernel(const float* __restrict__ x, const float* __restrict__ kern) {
    int b = blockIdx.x / C_, c = blockIdx.x % C_;
    __shared__ float xs[60][60];
    __shared__ float kf[3][25];
    int tid = threadIdx.x;  // 256
    for (int idx = tid; idx < 60*60; idx += 256) {
        int ry = idx / 60, rx = idx % 60;
        int hh = ry - 2, wi = rx - 2;
        float v = 0.f;
        if (hh >= 0 && hh < H_ && wi >= 0 && wi < W_)
            v = x[((size_t)(b*C_ + c)*H_ + hh)*W_ + wi];
        xs[ry][rx] = v;
    }
    if (tid < 75) kf[tid/25][tid%25] = kern[(c*3 + tid/25)*25 + tid%25];
    __syncthreads();
    for (int p = tid; p < P_; p += 256) {
        int hh = p / W_, wi = p % W_;
        float a0 = 0.f, a1 = 0.f, a2 = 0.f;
        #pragma unroll
        for (int ky = 0; ky < 5; ky++)
            #pragma unroll
            for (int kx = 0; kx < 5; kx++) {
                float v = xs[hh+ky][wi+kx];
                a0 += kf[0][ky*5+kx]*v;
                a1 += kf[1][ky*5+kx]*v;
                a2 += kf[2][ky*5+kx]*v;
            }
        a0 = fminf(fmaxf(a0, -3.f), 3.f);
        a1 = fminf(fmaxf(a1, -3.f), 3.f);
        a2 = fminf(fmaxf(a2, -3.f), 3.f);
        size_t base = ((size_t)b*3*C_ + c*3)*P_ + p;
        g_y[base        ] = a0;
        g_y[base +   P_ ] = a1;
        g_y[base + 2*P_ ] = a2;
    }
}

// ---------------- hf depthwise 3x3 ----------------
__global__ void dw_hf_kernel(const float* __restrict__ x, const float* __restrict__ kern) {
    int b = blockIdx.x / C_, c = blockIdx.x % C_;
    __shared__ float xs[58][58];
    __shared__ float kf[9];
    int tid = threadIdx.x;  // 256
    for (int idx = tid; idx < 58*58; idx += 256) {
        int ry = idx / 58, rx = idx % 58;
        int hh = ry - 1, wi = rx - 1;
        float v = 0.f;
        if (hh >= 0 && hh < H_ && wi >= 0 && wi < W_)
            v = x[((size_t)(b*C_ + c)*H_ + hh)*W_ + wi];
        xs[ry][rx] = v;
    }
    if (tid < 9) kf[tid] = kern[c*9 + tid];
    __syncthreads();
    for (int p = tid; p < P_; p += 256) {
        int hh = p / W_, wi = p % W_;
        float a = 0.f;
        #pragma unroll
        for (int ky = 0; ky < 3; ky++)
            #pragma unroll
            for (int kx = 0; kx < 3; kx++)
                a += kf[ky*3+kx] * xs[hh+ky][wi+kx];
        g_y[((size_t)(b*C_ + c))*P_ + p] = a;
    }
}

// ---------------- BN statistics over (B,H,W) per channel ----------------
__global__ void bn_stats2_kernel(int zsel) {
    const float* z = (zsel == 0) ? g_z1 : g_z2;
    int c = blockIdx.x;
    double s = 0.0, s2 = 0.0;
    for (int t = threadIdx.x; t < B_*(P_/4); t += 256) {
        int b = t / (P_/4), q = t % (P_/4);
        float4 v = ((const float4*)&z[((size_t)(b*C_ + c))*P_])[q];
        s  += (double)v.x + (double)v.y + (double)v.z + (double)v.w;
        s2 += (double)v.x*v.x + (double)v.y*v.y + (double)v.z*v.z + (double)v.w*v.w;
    }
    __shared__ double sh[256], sh2[256];
    sh[threadIdx.x] = s; sh2[threadIdx.x] = s2;
    __syncthreads();
    for (int st = 128; st > 0; st >>= 1) {
        if (threadIdx.x < st) { sh[threadIdx.x] += sh[threadIdx.x+st]; sh2[threadIdx.x] += sh2[threadIdx.x+st]; }
        __syncthreads();
    }
    if (threadIdx.x == 0) {
        double n = (double)B_*P_;
        double m = sh[0] / n;
        double var = sh2[0] / n - m*m;
        if (zsel == 0) { g_mean1[c] = (float)m; g_inv1[c] = (float)(1.0 / sqrt(var + 1e-5)); }
        else           { g_mean2[c] = (float)m; g_inv2[c] = (float)(1.0 / sqrt(var + 1e-5)); }
    }
}

// ---------------- BN apply + ReLU + gated accumulate ----------------
__global__ void bn_apply2_kernel(float* __restrict__ out, const float* __restrict__ gamma,
                                 const float* __restrict__ beta, int zsel, int sel) {
    int b = blockIdx.x / C_, c = blockIdx.x % C_;
    if (g_assign[b] != sel) return;
    const float* z = (zsel == 0) ? g_z1 : g_z2;
    float m   = (zsel == 0) ? g_mean1[c] : g_mean2[c];
    float inv = (zsel == 0) ? g_inv1[c]  : g_inv2[c];
    float sc = inv * gamma[c];
    float shft = beta[c] - m * sc;
    const float4* zp = (const float4*)&z[((size_t)(b*C_ + c))*P_];
    float4* op = (float4*)&out[((size_t)(b*C_ + c))*P_];
    for (int q = threadIdx.x; q < P_/4; q += 256) {
        float4 v = zp[q];
        float4 o = op[q];
        o.x += fmaxf(v.x*sc + shft, 0.f);
        o.y += fmaxf(v.y*sc + shft, 0.f);
        o.z += fmaxf(v.z*sc + shft, 0.f);
        o.w += fmaxf(v.w*sc + shft, 0.f);
        op[q] = o;
    }
}

// ---------------- launch (single stream, capture-safe) ----------------
extern "C" void kernel_launch(void* const* d_in, const int* in_sizes, int n_in,
                              void* d_out, int out_size) {
    const float* x          = (const float*)d_in[0];
    const float* Wg         = (const float*)d_in[1];
    const float* cd_w       = (const float*)d_in[2];
    const float* bayar_w    = (const float*)d_in[3];
    const float* srm_kernel = (const float*)d_in[4];
    const float* srm_out_w  = (const float*)d_in[5];
    const float* srm_gamma  = (const float*)d_in[6];
    const float* srm_beta   = (const float*)d_in[7];
    const float* hf_kernel  = (const float*)d_in[8];
    const float* hf_out_w   = (const float*)d_in[9];
    const float* hf_gamma   = (const float*)d_in[10];
    const float* hf_beta    = (const float*)d_in[11];
    const float* shared_w   = (const float*)d_in[12];
    float* out = (float*)d_out;

    int write_tail = ((size_t)out_size >= OUT_MAIN + 137) ? 1 : 0;

    // raise dynamic-smem limit for each conv instantiation (host-side, capture-safe)
    cudaFuncSetAttribute(conv_wmma_kernel<C_,3,1,false,0,0,true>,
                         cudaFuncAttributeMaxDynamicSharedMemorySize, SMEM_DYN);
    cudaFuncSetAttribute(conv_wmma_kernel<C_,5,2,true,0,0,false>,
                         cudaFuncAttributeMaxDynamicSharedMemorySize, SMEM_DYN);
    cudaFuncSetAttribute(conv_wmma_kernel<3*C_,1,0,false,1,1,false>,
                         cudaFuncAttributeMaxDynamicSharedMemorySize, SMEM_DYN);
    cudaFuncSetAttribute(conv_wmma_kernel<C_,1,0,false,1,2,false>,
                         cudaFuncAttributeMaxDynamicSharedMemorySize, SMEM_DYN);

    const dim3 cg(H_/2, B_);   // 28 x 32 blocks; each 128co x 128px (2 rows)

    pool_kernel<<<B_*C_, 256>>>(x);                                             // 1
    gate_kernel<<<1, 128>>>(Wg, out + OUT_MAIN, write_tail);                    // 2
    prep_shcd_kernel<<<64, 256>>>(shared_w, cd_w);                              // 3
    // fused shared(+cd for expert-0 samples) 3x3, full batch
    conv_wmma_kernel<C_,3,1,false,0,0,true><<<cg, 256, SMEM_DYN>>>(x, 0, out, -1);        // 4
    prep5_kernel<<<64, 256>>>(bayar_w, KOFF_BAYAR);                             // 5
    conv_wmma_kernel<C_,5,2,true,0,0,false><<<cg, 256, SMEM_DYN>>>(x, KOFF_BAYAR, out, 1);// 6

    // srm expert: full batch (BN stats), gated add
    dw_srm_kernel<<<B_*C_, 256>>>(x, srm_kernel);
    prep1_kernel<3*C_><<<192, 256>>>(srm_out_w, KOFF_SRM);
    conv_wmma_kernel<3*C_,1,0,false,1,1,false><<<cg, 256, SMEM_DYN>>>(x, KOFF_SRM, out, -1);
    bn_stats2_kernel<<<C_, 256>>>(0);
    bn_apply2_kernel<<<B_*C_, 256>>>(out, srm_gamma, srm_beta, 0, 2);

    // hf expert: full batch, gated add
    dw_hf_kernel<<<B_*C_, 256>>>(x, hf_kernel);
    prep1_kernel<C_><<<64, 256>>>(hf_out_w, KOFF_HF);
    conv_wmma_kernel<C_,1,0,false,1,2,false><<<cg, 256, SMEM_DYN>>>(x, KOFF_HF, out, -1);
    bn_stats2_kernel<<<C_, 256>>>(1);
    bn_apply2_kernel<<<B_*C_, 256>>>(out, hf_gamma, hf_beta, 1, 3);
}